// round 17
// baseline (speedup 1.0000x reference)
#include <cuda_runtime.h>
#include <cstdint>

#define BB 128
#define TT 4096
#define KK 64
#define CHUNK 64
#define NCH   (TT / CHUNK)   /* 64 chunks */

// scratch (static __device__: allocation-free)
__device__ __align__(16) uint8_t g_bp[(size_t)BB * TT * KK];   // 32 MB backpointers
__device__ int g_lasttag[BB];

// dynamic smem (forward)
struct Smem {
    float   ebuf[2][CHUNK * KK];         // 32 KB emission double buffer
    float   aslab[2][(CHUNK + 1) * KK];  // 32.5 KB alpha rows (row 0 = carry-in)
    float   bslab[2][CHUNK * KK];        // 32 KB per-step pre-emission max
    uint8_t bps[2][CHUNK * KK];          // 8 KB bp staging
};

__device__ __forceinline__ void cpasync16(uint32_t saddr, const void* gptr) {
    asm volatile("cp.async.ca.shared.global [%0], [%1], 16;" :: "r"(saddr), "l"(gptr));
}
__device__ __forceinline__ void cpasync_commit() { asm volatile("cp.async.commit_group;"); }
__device__ __forceinline__ void cpasync_wait1()  { asm volatile("cp.async.wait_group 1;"); }

__device__ __forceinline__ unsigned long long addx2(unsigned long long a, unsigned long long b) {
    unsigned long long d;
    asm("add.rn.f32x2 %0, %1, %2;" : "=l"(d) : "l"(a), "l"(b));
    return d;
}
__device__ __forceinline__ unsigned long long fma2(unsigned long long a, unsigned long long b,
                                                   unsigned long long c) {
    unsigned long long d;
    asm("fma.rn.f32x2 %0, %1, %2, %3;" : "=l"(d) : "l"(a), "l"(b), "l"(c));
    return d;
}
__device__ __forceinline__ float lo32(unsigned long long x) { return __uint_as_float((unsigned)x); }
__device__ __forceinline__ float hi32(unsigned long long x) { return __uint_as_float((unsigned)(x >> 32)); }
__device__ __forceinline__ unsigned long long pk2(float a, float b) {
    return (unsigned long long)__float_as_uint(a) | ((unsigned long long)__float_as_uint(b) << 32);
}

#define NEG1X2 0xBF800000BF800000ULL   /* (-1, -1) */
#define BIGX2  0x5F0000005F000000ULL   /* (2^63, 2^63) */

// =====================================================================
// Forward: VALUE = warps 0-1 (64 threads, thread k reduces all 64 preds);
// BP = warps 2-11, float-key first-index argmax with pass-local indices.
// Row distribution REBALANCED per pipe model: light pairs (SMSP 0,1)
// 7+8 rows, heavy pairs (SMSP 2,3) 17+16+16 -> fma pipe on 2/3 drops
// 175 -> ~153 cyc/step, matching the value-side alu bound (~154).
// =====================================================================
__global__ void __launch_bounds__(384, 1) fwd_kernel(const float* __restrict__ pot,
                                                     const float* __restrict__ trans) {
    extern __shared__ char smraw[];
    Smem* sm = (Smem*)smraw;

    const int b    = blockIdx.x;
    const int tid  = threadIdx.x;
    const int lane = tid & 31;
    const int wid  = tid >> 5;
    const bool isVal = (tid < 64);

    int k;
    if (isVal) k = tid;
    else       k = lane + (((wid - 2) & 1) ? 32 : 0);

    unsigned long long trp[32];
#pragma unroll
    for (int i = 0; i < 32; ++i)
        trp[i] = pk2(trans[(2 * i) * KK + k], trans[(2 * i + 1) * KK + k]);

    // bp-only: pass-local packed index constants (j, j+1), j = 0..15
    unsigned long long idxp[8];
    if (!isVal) {
#pragma unroll
        for (int i = 0; i < 8; ++i)
            idxp[i] = pk2((float)(2 * i), (float)(2 * i + 1));
    }

    int rstart = 0, rcnt = 0;
    if (!isVal) {
        int pi = (wid - 2) >> 1;
        if      (pi == 0) { rstart = 0;  rcnt = 17; }   // w2,w3   SMSP 2,3
        else if (pi == 1) { rstart = 17; rcnt = 7;  }   // w4,w5   SMSP 0,1
        else if (pi == 2) { rstart = 24; rcnt = 16; }   // w6,w7   SMSP 2,3
        else if (pi == 3) { rstart = 40; rcnt = 8;  }   // w8,w9   SMSP 0,1
        else              { rstart = 48; rcnt = 16; }   // w10,w11 SMSP 2,3
    }

    const float* pbm = pot + (size_t)b * TT * KK;

    if (isVal) {
        uint32_t s0 = (uint32_t)__cvta_generic_to_shared(sm->ebuf[0]);
        uint32_t s1 = (uint32_t)__cvta_generic_to_shared(sm->ebuf[1]);
#pragma unroll
        for (int i = 0; i < 16; ++i)
            cpasync16(s0 + (i * 64 + tid) * 16, pbm + (i * 64 + tid) * 4);
        cpasync_commit();
#pragma unroll
        for (int i = 0; i < 16; ++i)
            cpasync16(s1 + (i * 64 + tid) * 16, pbm + CHUNK * KK + (i * 64 + tid) * 4);
        cpasync_commit();
        cpasync_wait1();
    }
    __syncthreads();
    if (isVal)
        sm->aslab[0][KK + k] = sm->ebuf[0][k];

    for (int p = 0; p <= NCH; ++p) {
        const int pb = p & 1;

        if (isVal && p < NCH) {
            if (p > 0)
                sm->aslab[pb][k] = sm->aslab[pb ^ 1][CHUNK * KK + k];
            asm volatile("bar.sync 1, 64;" ::: "memory");

            const int r0 = (p == 0) ? 1 : 0;
            for (int r = r0; r < CHUNK; ++r) {
                const ulonglong2* arow = (const ulonglong2*)(sm->aslab[pb] + r * KK);
                float emit = sm->ebuf[pb][r * KK + k];

                float gm[4];
#pragma unroll
                for (int g = 0; g < 4; ++g) {
                    ulonglong2 s0 = arow[4 * g + 0], s1 = arow[4 * g + 1];
                    ulonglong2 s2 = arow[4 * g + 2], s3 = arow[4 * g + 3];
                    unsigned long long v0 = addx2(s0.x, trp[8 * g + 0]);
                    unsigned long long v1 = addx2(s0.y, trp[8 * g + 1]);
                    unsigned long long v2 = addx2(s1.x, trp[8 * g + 2]);
                    unsigned long long v3 = addx2(s1.y, trp[8 * g + 3]);
                    unsigned long long v4 = addx2(s2.x, trp[8 * g + 4]);
                    unsigned long long v5 = addx2(s2.y, trp[8 * g + 5]);
                    unsigned long long v6 = addx2(s3.x, trp[8 * g + 6]);
                    unsigned long long v7 = addx2(s3.y, trp[8 * g + 7]);
                    float m0 = fmaxf(lo32(v0), hi32(v0));
                    float m1 = fmaxf(lo32(v1), hi32(v1));
                    float m2 = fmaxf(lo32(v2), hi32(v2));
                    float m3 = fmaxf(lo32(v3), hi32(v3));
                    float m4 = fmaxf(lo32(v4), hi32(v4));
                    float m5 = fmaxf(lo32(v5), hi32(v5));
                    float m6 = fmaxf(lo32(v6), hi32(v6));
                    float m7 = fmaxf(lo32(v7), hi32(v7));
                    m0 = fmaxf(m0, m1); m2 = fmaxf(m2, m3);
                    m4 = fmaxf(m4, m5); m6 = fmaxf(m6, m7);
                    gm[g] = fmaxf(fmaxf(m0, m2), fmaxf(m4, m6));
                }
                float best = fmaxf(fmaxf(gm[0], gm[1]), fmaxf(gm[2], gm[3]));

                sm->bslab[pb][r * KK + k]       = best;
                sm->aslab[pb][(r + 1) * KK + k] = best + emit;
                asm volatile("bar.sync 1, 64;" ::: "memory");
            }

            if (p == NCH - 1 && tid == 0) {
                const float* fin = sm->aslab[pb] + CHUNK * KK;
                float bv = fin[0]; int bk = 0;
#pragma unroll
                for (int kk = 1; kk < KK; ++kk) {
                    float vv = fin[kk];
                    if (vv > bv) { bv = vv; bk = kk; }
                }
                g_lasttag[b] = bk;
            }

            if (p + 1 < NCH) {
                if (p + 2 < NCH) {
                    uint32_t sn = (uint32_t)__cvta_generic_to_shared(sm->ebuf[pb]);
                    const float* gsrc = pbm + (size_t)(p + 2) * CHUNK * KK;
#pragma unroll
                    for (int i = 0; i < 16; ++i)
                        cpasync16(sn + (i * 64 + tid) * 16, gsrc + (i * 64 + tid) * 4);
                }
                cpasync_commit();
                cpasync_wait1();
            }
        }

        if (!isVal && p >= 1) {
            const int q  = p - 1;
            const int qb = q & 1;

            for (int rr = 0; rr < rcnt; ++rr) {
                const int r = rstart + rr;
                if (q == 0 && r == 0) {
                    sm->bps[qb][k] = (uint8_t)k;   // placeholder (never applied)
                    continue;
                }
                const ulonglong2* arow = (const ulonglong2*)(sm->aslab[qb] + r * KK);
                float bestv = sm->bslab[qb][r * KK + k];
                unsigned long long bestp = pk2(bestv, bestv);

                float km[4];
#pragma unroll
                for (int g = 0; g < 4; ++g) {   // 16 preds per pass
                    ulonglong2 s0 = arow[4 * g + 0], s1 = arow[4 * g + 1];
                    ulonglong2 s2 = arow[4 * g + 2], s3 = arow[4 * g + 3];
                    unsigned long long vv[8];
                    vv[0] = addx2(s0.x, trp[8 * g + 0]);
                    vv[1] = addx2(s0.y, trp[8 * g + 1]);
                    vv[2] = addx2(s1.x, trp[8 * g + 2]);
                    vv[3] = addx2(s1.y, trp[8 * g + 3]);
                    vv[4] = addx2(s2.x, trp[8 * g + 4]);
                    vv[5] = addx2(s2.y, trp[8 * g + 5]);
                    vv[6] = addx2(s3.x, trp[8 * g + 6]);
                    vv[7] = addx2(s3.y, trp[8 * g + 7]);
                    float f[8];
#pragma unroll
                    for (int i = 0; i < 8; ++i) {
                        unsigned long long dp = fma2(vv[i], NEG1X2, bestp); // best - v
                        unsigned long long kp = fma2(dp, BIGX2, idxp[i]);   // local j
                        f[i] = fminf(lo32(kp), hi32(kp));
                    }
                    f[0] = fminf(f[0], f[1]); f[2] = fminf(f[2], f[3]);
                    f[4] = fminf(f[4], f[5]); f[6] = fminf(f[6], f[7]);
                    float kml = fminf(fminf(f[0], f[2]), fminf(f[4], f[6]));
                    km[g] = kml + (float)(16 * g);   // absolute index (exact <= 63)
                }
                float kmin = fminf(fminf(km[0], km[1]), fminf(km[2], km[3]));
                sm->bps[qb][r * KK + k] = (uint8_t)(int)kmin;
            }

            asm volatile("bar.sync 2, 320;" ::: "memory");
            {
                const int bpt = tid - 64;
                if (bpt < 256) {
                    uint4* dst = (uint4*)(g_bp + (size_t)b * TT * KK +
                                          (size_t)q * CHUNK * KK);
                    dst[bpt] = ((const uint4*)sm->bps[qb])[bpt];
                }
            }
        }
        __syncthreads();
    }
}

// =====================================================================
// Parallel backward (R15, passing): compose chunk maps -> boundary
// chase -> warp-parallel chunk walks -> lengths.
// =====================================================================
__global__ __launch_bounds__(256) void bwd_kernel(const int* __restrict__ mask,
                                                  float* __restrict__ out) {
    const int b    = blockIdx.x;
    const int tid  = threadIdx.x;
    const int wid  = tid >> 5;
    const int lane = tid & 31;

    __shared__ __align__(16) uint8_t cbuf[8][CHUNK * KK];  // 32 KB chunk buffers
    __shared__ __align__(16) uint8_t maps[NCH * KK];       // 4 KB composed maps
    __shared__ int   btag[NCH];
    __shared__ float tagbuf[8][CHUNK];

    const uint8_t* bpb = g_bp + (size_t)b * TT * KK;

    // ---- Phase A: compose 8 chunks per warp ----
    for (int i = 0; i < 8; ++i) {
        const int c = wid * 8 + i;
        const uint4* src = (const uint4*)(bpb + (size_t)c * CHUNK * KK);
        uint4* dst = (uint4*)cbuf[wid];
#pragma unroll
        for (int j = 0; j < 8; ++j) dst[lane + 32 * j] = src[lane + 32 * j];
        __syncwarp();

        int f0 = 2 * lane, f1 = 2 * lane + 1;   // identity seeds
#pragma unroll 4
        for (int r = CHUNK - 1; r >= 0; --r) {
            const uint8_t* row = cbuf[wid] + r * KK;
            f0 = row[f0];
            f1 = row[f1];
        }
        *(uint16_t*)(maps + c * KK + 2 * lane) = (uint16_t)(f0 | (f1 << 8));
        __syncwarp();
    }
    __syncthreads();

    // ---- Phase B: boundary chase ----
    if (tid == 0) {
        int cur = g_lasttag[b];
        btag[NCH - 1] = cur;
        for (int c = NCH - 1; c >= 1; --c) {
            cur = maps[c * KK + cur];
            btag[c - 1] = cur;
        }
    }
    __syncthreads();

    // ---- Phase C: parallel chunk walks ----
    for (int i = 0; i < 8; ++i) {
        const int c = wid * 8 + i;
        const uint4* src = (const uint4*)(bpb + (size_t)c * CHUNK * KK);
        uint4* dst = (uint4*)cbuf[wid];
#pragma unroll
        for (int j = 0; j < 8; ++j) dst[lane + 32 * j] = src[lane + 32 * j];
        __syncwarp();

        if (lane == 0) {
            int cur = btag[c];
            tagbuf[wid][CHUNK - 1] = (float)cur;
            for (int r = CHUNK - 1; r >= 1; --r) {
                cur = cbuf[wid][r * KK + cur];
                tagbuf[wid][r - 1] = (float)cur;
            }
        }
        __syncwarp();

        float2 o;
        o.x = tagbuf[wid][2 * lane];
        o.y = tagbuf[wid][2 * lane + 1];
        *(float2*)(out + (size_t)b * TT + c * CHUNK + 2 * lane) = o;
        __syncwarp();
    }

    // ---- Phase D: sequence length ----
    {
        int s = 0;
        const int4* m = (const int4*)(mask + (size_t)b * TT);
        for (int i = tid; i < TT / 4; i += 256) {
            int4 v = m[i];
            s += v.x + v.y + v.z + v.w;
        }
#pragma unroll
        for (int off = 16; off; off >>= 1) s += __shfl_xor_sync(0xffffffffu, s, off);
        __shared__ int red[8];
        if ((tid & 31) == 0) red[tid >> 5] = s;
        __syncthreads();
        if (tid == 0) {
            int tot = 0;
#pragma unroll
            for (int i = 0; i < 8; ++i) tot += red[i];
            out[(size_t)BB * TT + b] = (float)tot;
        }
    }
}

// =====================================================================
extern "C" void kernel_launch(void* const* d_in, const int* in_sizes, int n_in,
                              void* d_out, int out_size) {
    const float* pot   = nullptr;
    const float* trans = nullptr;
    const int*   mask  = nullptr;
    for (int i = 0; i < n_in; ++i) {
        if      (in_sizes[i] == BB * TT * KK) pot   = (const float*)d_in[i];
        else if (in_sizes[i] == KK * KK)      trans = (const float*)d_in[i];
        else if (in_sizes[i] == BB * TT)      mask  = (const int*)  d_in[i];
    }
    float* out = (float*)d_out;   // [tags (128*4096) | lengths (128)] as f32

    cudaFuncSetAttribute(fwd_kernel, cudaFuncAttributeMaxDynamicSharedMemorySize,
                         (int)sizeof(Smem));
    fwd_kernel<<<BB, 384, sizeof(Smem)>>>(pot, trans);
    bwd_kernel<<<BB, 256>>>(mask, out);
}